// round 11
// baseline (speedup 1.0000x reference)
#include <cuda_runtime.h>
#include <math.h>

// ---------------------------------------------------------------------------
// Problem constants
//   tokens [256,32] i32, emb [32000,256], W_ih/W_hh [4,256,256],
//   b_ih/b_hh [4,256], dec_W [32000,256], dec_b [32000]
//   out = decoded [256,32,32000] f32  ++  hidden [4,32,256] f32
// ---------------------------------------------------------------------------
#define T_STEPS 256
#define BATCH   32
#define HID     256
#define NVOC    32000
#define M_TOT   (T_STEPS * BATCH)          // 8192

// Scratch (static __device__ — no allocations allowed)
static __device__ float  g_AT[HID * M_TOT];          // top outputs, K-major: [h][t*B+b]  (8 MB)
static __device__ float  g_BT[HID * NVOC];           // dec_W transposed:   [h][v]        (32 MB)
static __device__ float4 g_Wih4[4 * 128 * 128];      // packed W_ih (1 MB)
static __device__ float4 g_Whh4[4 * 128 * 128];      // packed W_hh (1 MB)

// ---------------------------------------------------------------------------
// Packed f32x2 helpers (Blackwell FFMA2 — 2x fp32 rate, PTX-only)
// ---------------------------------------------------------------------------
__device__ __forceinline__ unsigned long long f2pack(float lo, float hi) {
    unsigned long long r;
    asm("mov.b64 %0, {%1, %2};" : "=l"(r) : "f"(lo), "f"(hi));
    return r;
}
__device__ __forceinline__ void f2fma(unsigned long long& d,
                                      unsigned long long a, unsigned long long b) {
    asm("fma.rn.f32x2 %0, %1, %2, %0;" : "+l"(d) : "l"(a), "l"(b));
}
__device__ __forceinline__ float2 f2unpack(unsigned long long v) {
    unsigned int lo, hi;
    asm("mov.b64 {%0, %1}, %2;" : "=r"(lo), "=r"(hi) : "l"(v));
    return make_float2(__uint_as_float(lo), __uint_as_float(hi));
}

// ---------------------------------------------------------------------------
// Weight packing: Wq[l][d2][jp] = (W[2jp][2d2], W[2jp+1][2d2],
//                                  W[2jp][2d2+1], W[2jp+1][2d2+1])
// -> inner loop does coalesced LDG.128 over jp, feeds f32x2 FMAs.
// ---------------------------------------------------------------------------
__global__ void pack_weights(const float* __restrict__ Wih,
                             const float* __restrict__ Whh) {
    int idx = blockIdx.x * blockDim.x + threadIdx.x;   // 0..65535
    int jp = idx & 127;
    int d2 = (idx >> 7) & 127;
    int l  = idx >> 14;
    int j0 = 2 * jp, d0 = 2 * d2;
    const float* A = Wih + l * 65536;
    const float* B = Whh + l * 65536;
    float4 v;
    v.x = A[j0 * 256 + d0];       v.y = A[(j0 + 1) * 256 + d0];
    v.z = A[j0 * 256 + d0 + 1];   v.w = A[(j0 + 1) * 256 + d0 + 1];
    g_Wih4[idx] = v;
    v.x = B[j0 * 256 + d0];       v.y = B[(j0 + 1) * 256 + d0];
    v.z = B[j0 * 256 + d0 + 1];   v.w = B[(j0 + 1) * 256 + d0 + 1];
    g_Whh4[idx] = v;
}

// dec_W [32000,256] -> g_BT [256][32000] (tiled shared transpose)
__global__ void transpose_decW(const float* __restrict__ W) {
    __shared__ float tile[32][33];
    int r0 = blockIdx.y * 32;      // vocab rows
    int c0 = blockIdx.x * 32;      // hid cols
    int x = threadIdx.x, y = threadIdx.y;
#pragma unroll
    for (int j = 0; j < 32; j += 8)
        tile[y + j][x] = W[(size_t)(r0 + y + j) * 256 + c0 + x];
    __syncthreads();
#pragma unroll
    for (int j = 0; j < 32; j += 8)
        g_BT[(size_t)(c0 + y + j) * NVOC + r0 + x] = tile[x][y + j];
}

// ---------------------------------------------------------------------------
// RNN: one CTA per batch element (batches are fully independent -> no grid
// sync). 256 threads: tid<128 computes the W_ih half for j-pair tid,
// tid>=128 the W_hh half; combined + tanh in SMEM.
// Writes top-layer outputs directly into K-major g_AT, final hidden to d_out.
// ---------------------------------------------------------------------------
__global__ __launch_bounds__(256) void rnn_kernel(
    const int*   __restrict__ tokens,
    const float* __restrict__ emb,
    const float* __restrict__ b_ih,
    const float* __restrict__ b_hh,
    float*       __restrict__ out_hidden)
{
    __shared__ __align__(16) float  xs[256];
    __shared__ __align__(16) float  hs[4][256];
    __shared__ __align__(16) float2 part[128];
    __shared__ __align__(16) float  nh[256];

    const int b   = blockIdx.x;
    const int tid = threadIdx.x;
    const int jp  = tid & 127;
    const bool ih = tid < 128;

#pragma unroll
    for (int l = 0; l < 4; l++) hs[l][tid] = 0.0f;
    __syncthreads();

    for (int t = 0; t < T_STEPS; t++) {
        int tok = tokens[t * BATCH + b];
        xs[tid] = emb[(size_t)tok * 256 + tid];
        __syncthreads();

        for (int l = 0; l < 4; l++) {
            const float*  src = ih ? xs : hs[l];
            const float4* Wp  = (ih ? g_Wih4 : g_Whh4) + l * 16384 + jp;
            unsigned long long acc0 = 0ull, acc1 = 0ull;
#pragma unroll 4
            for (int d2 = 0; d2 < 128; d2 += 2) {
                float2 s0 = *(const float2*)(src + 2 * d2);
                float2 s1 = *(const float2*)(src + 2 * d2 + 2);
                float4 w0 = Wp[d2 * 128];
                float4 w1 = Wp[(d2 + 1) * 128];
                f2fma(acc0, f2pack(s0.x, s0.x), f2pack(w0.x, w0.y));
                f2fma(acc1, f2pack(s0.y, s0.y), f2pack(w0.z, w0.w));
                f2fma(acc0, f2pack(s1.x, s1.x), f2pack(w1.x, w1.y));
                f2fma(acc1, f2pack(s1.y, s1.y), f2pack(w1.z, w1.w));
            }
            float2 pa = f2unpack(acc0), pb = f2unpack(acc1);
            float2 r  = make_float2(pa.x + pb.x, pa.y + pb.y);
            if (!ih) part[jp] = r;
            __syncthreads();
            if (ih) {
                float2 hh = part[jp];
                int j0 = l * 256 + 2 * jp;
                float v0 = r.x + hh.x + b_ih[j0]     + b_hh[j0];
                float v1 = r.y + hh.y + b_ih[j0 + 1] + b_hh[j0 + 1];
                nh[2 * jp]     = tanhf(v0);
                nh[2 * jp + 1] = tanhf(v1);
            }
            __syncthreads();
            float v = nh[tid];
            hs[l][tid] = v;    // carry for next t
            xs[tid]    = v;    // input to next layer
            __syncthreads();
        }
        // top-layer output, K-major scratch for the decoder GEMM
        g_AT[tid * M_TOT + t * BATCH + b] = xs[tid];
    }
#pragma unroll
    for (int l = 0; l < 4; l++)
        out_hidden[(l * BATCH + b) * 256 + tid] = hs[l][tid];
}

// ---------------------------------------------------------------------------
// Decoder GEMM: C[8192,32000] = A[8192,256] @ dec_W[32000,256]^T + dec_b
// Both operands pre-transposed to K-major -> conflict-free tile staging.
// BM=BN=128, BK=32, 256 threads, 8x8 per thread, all math through FFMA2.
// ---------------------------------------------------------------------------
__global__ __launch_bounds__(256) void gemm_dec(
    const float* __restrict__ dec_b, float* __restrict__ out)
{
    __shared__ __align__(16) float As[32][128];
    __shared__ __align__(16) float Bs[32][128];

    const int n_base = blockIdx.x * 128;
    const int m_base = blockIdx.y * 128;
    const int tid = threadIdx.x;
    const int tx  = tid & 15, ty = tid >> 4;
    const int r   = tid >> 3, q  = tid & 7;

    unsigned long long acc[4][8];
#pragma unroll
    for (int i = 0; i < 4; i++)
#pragma unroll
        for (int j = 0; j < 8; j++) acc[i][j] = 0ull;

    for (int kc = 0; kc < 256; kc += 32) {
        const float* Ag = g_AT + (kc + r) * M_TOT + m_base;
        const float* Bg = g_BT + (size_t)(kc + r) * NVOC + n_base;
#pragma unroll
        for (int s = 0; s < 4; s++) {
            int p = (q + 8 * s) * 4;
            *(float4*)&As[r][p] = *(const float4*)(Ag + p);
            *(float4*)&Bs[r][p] = *(const float4*)(Bg + p);
        }
        __syncthreads();
#pragma unroll
        for (int kk = 0; kk < 32; kk++) {
            float4 a0 = *(const float4*)&As[kk][ty * 8];
            float4 a1 = *(const float4*)&As[kk][ty * 8 + 4];
            float4 b0 = *(const float4*)&Bs[kk][tx * 8];
            float4 b1 = *(const float4*)&Bs[kk][tx * 8 + 4];
            unsigned long long ap[4];
            ap[0] = f2pack(a0.x, a0.y); ap[1] = f2pack(a0.z, a0.w);
            ap[2] = f2pack(a1.x, a1.y); ap[3] = f2pack(a1.z, a1.w);
            float bv[8] = {b0.x, b0.y, b0.z, b0.w, b1.x, b1.y, b1.z, b1.w};
#pragma unroll
            for (int j = 0; j < 8; j++) {
                unsigned long long bd = f2pack(bv[j], bv[j]);
#pragma unroll
                for (int i = 0; i < 4; i++) f2fma(acc[i][j], ap[i], bd);
            }
        }
        __syncthreads();
    }

    float bias[8];
#pragma unroll
    for (int j = 0; j < 8; j++) bias[j] = dec_b[n_base + tx * 8 + j];

#pragma unroll
    for (int i2 = 0; i2 < 4; i2++) {
        float2 v[8];
#pragma unroll
        for (int j = 0; j < 8; j++) v[j] = f2unpack(acc[i2][j]);
        size_t row0 = (size_t)(m_base + ty * 8 + 2 * i2) * NVOC + n_base + tx * 8;
        size_t row1 = row0 + NVOC;
        float4 o;
        o = make_float4(v[0].x + bias[0], v[1].x + bias[1], v[2].x + bias[2], v[3].x + bias[3]);
        *(float4*)(out + row0) = o;
        o = make_float4(v[4].x + bias[4], v[5].x + bias[5], v[6].x + bias[6], v[7].x + bias[7]);
        *(float4*)(out + row0 + 4) = o;
        o = make_float4(v[0].y + bias[0], v[1].y + bias[1], v[2].y + bias[2], v[3].y + bias[3]);
        *(float4*)(out + row1) = o;
        o = make_float4(v[4].y + bias[4], v[5].y + bias[5], v[6].y + bias[6], v[7].y + bias[7]);
        *(float4*)(out + row1 + 4) = o;
    }
}

// ---------------------------------------------------------------------------
extern "C" void kernel_launch(void* const* d_in, const int* in_sizes, int n_in,
                              void* d_out, int out_size) {
    const int*   tokens = (const int*)  d_in[0];
    const float* emb    = (const float*)d_in[1];
    const float* W_ih   = (const float*)d_in[2];
    const float* W_hh   = (const float*)d_in[3];
    const float* b_ih   = (const float*)d_in[4];
    const float* b_hh   = (const float*)d_in[5];
    const float* dec_W  = (const float*)d_in[6];
    const float* dec_b  = (const float*)d_in[7];
    (void)in_sizes; (void)n_in; (void)out_size;

    float* out        = (float*)d_out;
    float* out_hidden = out + (size_t)M_TOT * NVOC;   // decoded ++ hidden

    pack_weights<<<256, 256>>>(W_ih, W_hh);
    transpose_decW<<<dim3(8, 1000), dim3(32, 8)>>>(dec_W);
    rnn_kernel<<<BATCH, 256>>>(tokens, emb, b_ih, b_hh, out_hidden);
    gemm_dec<<<dim3(NVOC / 128, M_TOT / 128), 256>>>(dec_b, out);
}

// round 13
// speedup vs baseline: 1.0016x; 1.0016x over previous
#include <cuda_runtime.h>
#include <math.h>

// ---------------------------------------------------------------------------
// Problem constants
//   tokens [256,32] i32, emb [32000,256], W_ih/W_hh [4,256,256],
//   b_ih/b_hh [4,256], dec_W [32000,256], dec_b [32000]
//   out = decoded [256,32,32000] f32  ++  hidden [4,32,256] f32
// ---------------------------------------------------------------------------
#define T_STEPS 256
#define BATCH   32
#define HID     256
#define NVOC    32000
#define M_TOT   (T_STEPS * BATCH)          // 8192

// Scratch (static __device__ — no allocations allowed)
static __device__ float  g_AT[HID * M_TOT];          // top outputs, K-major: [h][t*B+b]  (8 MB)
static __device__ float  g_BT[HID * NVOC];           // dec_W transposed:   [h][v]        (32 MB)
static __device__ float4 g_Wih4[4 * 128 * 128];      // packed W_ih (1 MB)
static __device__ float4 g_Whh4[4 * 128 * 128];      // packed W_hh (1 MB)

// ---------------------------------------------------------------------------
// Packed f32x2 helpers (Blackwell FFMA2 — 2x fp32 rate, PTX-only)
// ---------------------------------------------------------------------------
__device__ __forceinline__ unsigned long long f2pack(float lo, float hi) {
    unsigned long long r;
    asm("mov.b64 %0, {%1, %2};" : "=l"(r) : "f"(lo), "f"(hi));
    return r;
}
__device__ __forceinline__ void f2fma(unsigned long long& d,
                                      unsigned long long a, unsigned long long b) {
    asm("fma.rn.f32x2 %0, %1, %2, %0;" : "+l"(d) : "l"(a), "l"(b));
}
__device__ __forceinline__ float2 f2unpack(unsigned long long v) {
    unsigned int lo, hi;
    asm("mov.b64 {%0, %1}, %2;" : "=r"(lo), "=r"(hi) : "l"(v));
    return make_float2(__uint_as_float(lo), __uint_as_float(hi));
}

// ---------------------------------------------------------------------------
// Weight packing: Wq[l][d2][jp] = (W[2jp][2d2], W[2jp+1][2d2],
//                                  W[2jp][2d2+1], W[2jp+1][2d2+1])
// -> inner loop does coalesced LDG.128 over jp, feeds f32x2 FMAs.
// ---------------------------------------------------------------------------
__global__ void pack_weights(const float* __restrict__ Wih,
                             const float* __restrict__ Whh) {
    int idx = blockIdx.x * blockDim.x + threadIdx.x;   // 0..65535
    int jp = idx & 127;
    int d2 = (idx >> 7) & 127;
    int l  = idx >> 14;
    int j0 = 2 * jp, d0 = 2 * d2;
    const float* A = Wih + l * 65536;
    const float* B = Whh + l * 65536;
    float4 v;
    v.x = A[j0 * 256 + d0];       v.y = A[(j0 + 1) * 256 + d0];
    v.z = A[j0 * 256 + d0 + 1];   v.w = A[(j0 + 1) * 256 + d0 + 1];
    g_Wih4[idx] = v;
    v.x = B[j0 * 256 + d0];       v.y = B[(j0 + 1) * 256 + d0];
    v.z = B[j0 * 256 + d0 + 1];   v.w = B[(j0 + 1) * 256 + d0 + 1];
    g_Whh4[idx] = v;
}

// dec_W [32000,256] -> g_BT [256][32000] (tiled shared transpose)
__global__ void transpose_decW(const float* __restrict__ W) {
    __shared__ float tile[32][33];
    int r0 = blockIdx.y * 32;      // vocab rows
    int c0 = blockIdx.x * 32;      // hid cols
    int x = threadIdx.x, y = threadIdx.y;
#pragma unroll
    for (int j = 0; j < 32; j += 8)
        tile[y + j][x] = W[(size_t)(r0 + y + j) * 256 + c0 + x];
    __syncthreads();
#pragma unroll
    for (int j = 0; j < 32; j += 8)
        g_BT[(size_t)(c0 + y + j) * NVOC + r0 + x] = tile[x][y + j];
}

// ---------------------------------------------------------------------------
// RNN: one CTA per batch element (batches are fully independent -> no grid
// sync). 256 threads: tid<128 computes the W_ih half for j-pair tid,
// tid>=128 the W_hh half; combined + tanh in SMEM.
// Writes top-layer outputs directly into K-major g_AT, final hidden to d_out.
// ---------------------------------------------------------------------------
__global__ __launch_bounds__(256) void rnn_kernel(
    const int*   __restrict__ tokens,
    const float* __restrict__ emb,
    const float* __restrict__ b_ih,
    const float* __restrict__ b_hh,
    float*       __restrict__ out_hidden)
{
    __shared__ __align__(16) float  xs[256];
    __shared__ __align__(16) float  hs[4][256];
    __shared__ __align__(16) float2 part[128];
    __shared__ __align__(16) float  nh[256];

    const int b   = blockIdx.x;
    const int tid = threadIdx.x;
    const int jp  = tid & 127;
    const bool ih = tid < 128;

#pragma unroll
    for (int l = 0; l < 4; l++) hs[l][tid] = 0.0f;
    __syncthreads();

    for (int t = 0; t < T_STEPS; t++) {
        int tok = tokens[t * BATCH + b];
        xs[tid] = emb[(size_t)tok * 256 + tid];
        __syncthreads();

        for (int l = 0; l < 4; l++) {
            const float*  src = ih ? xs : hs[l];
            const float4* Wp  = (ih ? g_Wih4 : g_Whh4) + l * 16384 + jp;
            unsigned long long acc0 = 0ull, acc1 = 0ull;
#pragma unroll 4
            for (int d2 = 0; d2 < 128; d2 += 2) {
                float2 s0 = *(const float2*)(src + 2 * d2);
                float2 s1 = *(const float2*)(src + 2 * d2 + 2);
                float4 w0 = Wp[d2 * 128];
                float4 w1 = Wp[(d2 + 1) * 128];
                f2fma(acc0, f2pack(s0.x, s0.x), f2pack(w0.x, w0.y));
                f2fma(acc1, f2pack(s0.y, s0.y), f2pack(w0.z, w0.w));
                f2fma(acc0, f2pack(s1.x, s1.x), f2pack(w1.x, w1.y));
                f2fma(acc1, f2pack(s1.y, s1.y), f2pack(w1.z, w1.w));
            }
            float2 pa = f2unpack(acc0), pb = f2unpack(acc1);
            float2 r  = make_float2(pa.x + pb.x, pa.y + pb.y);
            if (!ih) part[jp] = r;
            __syncthreads();
            if (ih) {
                float2 hh = part[jp];
                int j0 = l * 256 + 2 * jp;
                float v0 = r.x + hh.x + b_ih[j0]     + b_hh[j0];
                float v1 = r.y + hh.y + b_ih[j0 + 1] + b_hh[j0 + 1];
                nh[2 * jp]     = tanhf(v0);
                nh[2 * jp + 1] = tanhf(v1);
            }
            __syncthreads();
            float v = nh[tid];
            hs[l][tid] = v;    // carry for next t
            xs[tid]    = v;    // input to next layer
            __syncthreads();
        }
        // top-layer output, K-major scratch for the decoder GEMM
        g_AT[tid * M_TOT + t * BATCH + b] = xs[tid];
    }
#pragma unroll
    for (int l = 0; l < 4; l++)
        out_hidden[(l * BATCH + b) * 256 + tid] = hs[l][tid];
}

// ---------------------------------------------------------------------------
// Decoder GEMM: C[8192,32000] = A[8192,256] @ dec_W[32000,256]^T + dec_b
// Both operands pre-transposed to K-major -> conflict-free tile staging.
// BM=BN=128, BK=32, 256 threads, 8x8 per thread, all math through FFMA2.
// ---------------------------------------------------------------------------
__global__ __launch_bounds__(256) void gemm_dec(
    const float* __restrict__ dec_b, float* __restrict__ out)
{
    __shared__ __align__(16) float As[32][128];
    __shared__ __align__(16) float Bs[32][128];

    const int n_base = blockIdx.x * 128;
    const int m_base = blockIdx.y * 128;
    const int tid = threadIdx.x;
    const int tx  = tid & 15, ty = tid >> 4;
    const int r   = tid >> 3, q  = tid & 7;

    unsigned long long acc[4][8];
#pragma unroll
    for (int i = 0; i < 4; i++)
#pragma unroll
        for (int j = 0; j < 8; j++) acc[i][j] = 0ull;

    for (int kc = 0; kc < 256; kc += 32) {
        const float* Ag = g_AT + (kc + r) * M_TOT + m_base;
        const float* Bg = g_BT + (size_t)(kc + r) * NVOC + n_base;
#pragma unroll
        for (int s = 0; s < 4; s++) {
            int p = (q + 8 * s) * 4;
            *(float4*)&As[r][p] = *(const float4*)(Ag + p);
            *(float4*)&Bs[r][p] = *(const float4*)(Bg + p);
        }
        __syncthreads();
#pragma unroll
        for (int kk = 0; kk < 32; kk++) {
            float4 a0 = *(const float4*)&As[kk][ty * 8];
            float4 a1 = *(const float4*)&As[kk][ty * 8 + 4];
            float4 b0 = *(const float4*)&Bs[kk][tx * 8];
            float4 b1 = *(const float4*)&Bs[kk][tx * 8 + 4];
            unsigned long long ap[4];
            ap[0] = f2pack(a0.x, a0.y); ap[1] = f2pack(a0.z, a0.w);
            ap[2] = f2pack(a1.x, a1.y); ap[3] = f2pack(a1.z, a1.w);
            float bv[8] = {b0.x, b0.y, b0.z, b0.w, b1.x, b1.y, b1.z, b1.w};
#pragma unroll
            for (int j = 0; j < 8; j++) {
                unsigned long long bd = f2pack(bv[j], bv[j]);
#pragma unroll
                for (int i = 0; i < 4; i++) f2fma(acc[i][j], ap[i], bd);
            }
        }
        __syncthreads();
    }

    float bias[8];
#pragma unroll
    for (int j = 0; j < 8; j++) bias[j] = dec_b[n_base + tx * 8 + j];

#pragma unroll
    for (int i2 = 0; i2 < 4; i2++) {
        float2 v[8];
#pragma unroll
        for (int j = 0; j < 8; j++) v[j] = f2unpack(acc[i2][j]);
        size_t row0 = (size_t)(m_base + ty * 8 + 2 * i2) * NVOC + n_base + tx * 8;
        size_t row1 = row0 + NVOC;
        float4 o;
        o = make_float4(v[0].x + bias[0], v[1].x + bias[1], v[2].x + bias[2], v[3].x + bias[3]);
        *(float4*)(out + row0) = o;
        o = make_float4(v[4].x + bias[4], v[5].x + bias[5], v[6].x + bias[6], v[7].x + bias[7]);
        *(float4*)(out + row0 + 4) = o;
        o = make_float4(v[0].y + bias[0], v[1].y + bias[1], v[2].y + bias[2], v[3].y + bias[3]);
        *(float4*)(out + row1) = o;
        o = make_float4(v[4].y + bias[4], v[5].y + bias[5], v[6].y + bias[6], v[7].y + bias[7]);
        *(float4*)(out + row1 + 4) = o;
    }
}

// ---------------------------------------------------------------------------
extern "C" void kernel_launch(void* const* d_in, const int* in_sizes, int n_in,
                              void* d_out, int out_size) {
    const int*   tokens = (const int*)  d_in[0];
    const float* emb    = (const float*)d_in[1];
    const float* W_ih   = (const float*)d_in[2];
    const float* W_hh   = (const float*)d_in[3];
    const float* b_ih   = (const float*)d_in[4];
    const float* b_hh   = (const float*)d_in[5];
    const float* dec_W  = (const float*)d_in[6];
    const float* dec_b  = (const float*)d_in[7];
    (void)in_sizes; (void)n_in; (void)out_size;

    float* out        = (float*)d_out;
    float* out_hidden = out + (size_t)M_TOT * NVOC;   // decoded ++ hidden

    pack_weights<<<256, 256>>>(W_ih, W_hh);
    transpose_decW<<<dim3(8, 1000), dim3(32, 8)>>>(dec_W);
    rnn_kernel<<<BATCH, 256>>>(tokens, emb, b_ih, b_hh, out_hidden);
    gemm_dec<<<dim3(NVOC / 128, M_TOT / 128), 256>>>(dec_b, out);
}

// round 16
// speedup vs baseline: 1.6880x; 1.6853x over previous
#include <cuda_runtime.h>
#include <math.h>
#include <stdint.h>

#define T_STEPS 256
#define BATCH   32
#define NVOC    32000
#define M_TOT   (T_STEPS * BATCH)   // 8192

typedef unsigned long long ull;

// Static scratch (no allocations allowed)
static __device__ float  g_A[M_TOT * 256];            // RNN top outputs [m][k] (8 MB)
static __device__ float4 g_Wq[4 * 2 * 128 * 128];     // packed RNN weights (2 MB)

// ---------------------------------------------------------------------------
// helpers
// ---------------------------------------------------------------------------
__device__ __forceinline__ ull f2pack(float lo, float hi) {
    ull r; asm("mov.b64 %0, {%1, %2};" : "=l"(r) : "f"(lo), "f"(hi)); return r;
}
__device__ __forceinline__ void f2fma(ull& d, ull a, ull b) {
    asm("fma.rn.f32x2 %0, %1, %2, %0;" : "+l"(d) : "l"(a), "l"(b));
}
__device__ __forceinline__ float2 f2unpack(ull v) {
    unsigned lo, hi;
    asm("mov.b64 {%0, %1}, %2;" : "=r"(lo), "=r"(hi) : "l"(v));
    return make_float2(__uint_as_float(lo), __uint_as_float(hi));
}
__device__ __forceinline__ uint32_t smem_u32(const void* p) {
    uint32_t a;
    asm("{ .reg .u64 t; cvta.to.shared.u64 t, %1; cvt.u32.u64 %0, t; }" : "=r"(a) : "l"(p));
    return a;
}
__device__ __forceinline__ void cluster_sync_() {
    asm volatile("barrier.cluster.arrive.aligned;\n\tbarrier.cluster.wait.aligned;" ::: "memory");
}
__device__ __forceinline__ void st_cluster64(uint32_t laddr, uint32_t rk, ull v) {
    asm volatile("{\n\t.reg .b32 ra;\n\tmapa.shared::cluster.u32 ra, %0, %1;\n\t"
                 "st.shared::cluster.u64 [ra], %2;\n\t}" :: "r"(laddr), "r"(rk), "l"(v) : "memory");
}
__device__ __forceinline__ uint32_t cvt_tf32(float x) {
    uint32_t u; asm("cvt.rna.tf32.f32 %0, %1;" : "=r"(u) : "f"(x)); return u;
}
__device__ __forceinline__ void mma_tf32_16x8x8(float* c, const uint32_t* a, const uint32_t* b) {
    asm volatile("mma.sync.aligned.m16n8k8.row.col.f32.tf32.tf32.f32 "
                 "{%0,%1,%2,%3}, {%4,%5,%6,%7}, {%8,%9}, {%0,%1,%2,%3};"
                 : "+f"(c[0]), "+f"(c[1]), "+f"(c[2]), "+f"(c[3])
                 : "r"(a[0]), "r"(a[1]), "r"(a[2]), "r"(a[3]), "r"(b[0]), "r"(b[1]));
}

// ---------------------------------------------------------------------------
// RNN weight packing: g_Wq[((l*2+m)*128 + d2)*128 + jpg] =
//   ( W[2jpg][2d2], W[2jpg+1][2d2], W[2jpg][2d2+1], W[2jpg+1][2d2+1] )
// ---------------------------------------------------------------------------
__global__ void pack_rnn(const float* __restrict__ Wih, const float* __restrict__ Whh) {
    int idx = blockIdx.x * blockDim.x + threadIdx.x;   // 0..131071
    int jpg = idx & 127, d2 = (idx >> 7) & 127, m = (idx >> 14) & 1, l = idx >> 15;
    const float* W = (m ? Whh : Wih) + l * 65536;
    int j0 = 2 * jpg, d0 = 2 * d2;
    float4 v;
    v.x = W[j0 * 256 + d0];       v.y = W[(j0 + 1) * 256 + d0];
    v.z = W[j0 * 256 + d0 + 1];   v.w = W[(j0 + 1) * 256 + d0 + 1];
    g_Wq[idx] = v;
}

// ---------------------------------------------------------------------------
// RNN: 16 clusters x 4 CTAs; cluster c handles batches {2c, 2c+1}; rank r
// owns j in [64r, 64r+64). h state replicated per-CTA in SMEM as batch-paired
// duplicated u64, double buffered by timestep parity -> one cluster barrier
// per layer. Thread (m,q,jp): matrix m, d-chunk q, local j-pair jp.
// ---------------------------------------------------------------------------
__global__ __launch_bounds__(256) __cluster_dims__(4, 1, 1)
void rnn_kernel(const int*   __restrict__ tokens,
                const float* __restrict__ emb,
                const float* __restrict__ b_ih,
                const float* __restrict__ b_hh,
                float*       __restrict__ out_hidden)
{
    __shared__ __align__(16) ull   hs[2][4][2][256];   // [parity][layer][batch][d] dup'd
    __shared__ __align__(16) ull   embdup[2][256];
    __shared__ __align__(16) ull   part[2][8][32];     // [batch][group][jp]
    __shared__ float bsum[4][256];

    const int tid = threadIdx.x;
    const int cid = blockIdx.x >> 2;
    uint32_t rank; asm("mov.u32 %0, %%cluster_ctarank;" : "=r"(rank));
    const int m  = tid >> 7;
    const int q  = (tid >> 5) & 3;
    const int jp = tid & 31;
    const int g  = m * 4 + q;
    const int jpg = 32 * (int)rank + jp;

#pragma unroll
    for (int l = 0; l < 4; l++) bsum[l][tid] = b_ih[l * 256 + tid] + b_hh[l * 256 + tid];
    {
        ull* z = &hs[1][0][0][0];
#pragma unroll
        for (int i = 0; i < 8; i++) z[i * 256 + tid] = 0ull;
    }
    __syncthreads();
    cluster_sync_();

    for (int t = 0; t < T_STEPS; t++) {
        const int pnew = t & 1, pold = pnew ^ 1;
        {
            int tk0 = __ldg(tokens + t * 32 + 2 * cid);
            int tk1 = __ldg(tokens + t * 32 + 2 * cid + 1);
            float e0 = __ldg(emb + (size_t)tk0 * 256 + tid);
            float e1 = __ldg(emb + (size_t)tk1 * 256 + tid);
            embdup[0][tid] = f2pack(e0, e0);
            embdup[1][tid] = f2pack(e1, e1);
        }
        __syncthreads();

        for (int l = 0; l < 4; l++) {
            const ull *s0, *s1;
            if (m)           { s0 = hs[pold][l][0];     s1 = hs[pold][l][1]; }
            else if (l == 0) { s0 = embdup[0];          s1 = embdup[1]; }
            else             { s0 = hs[pnew][l - 1][0]; s1 = hs[pnew][l - 1][1]; }
            const float4* w = g_Wq + (size_t)((l * 2 + m) * 128) * 128 + jpg;
            ull a0 = 0ull, a1 = 0ull;
#pragma unroll 8
            for (int d2 = 32 * q; d2 < 32 * q + 32; d2++) {
                float4 wq = __ldg(&w[(size_t)d2 * 128]);
                ulonglong2 x0 = *(const ulonglong2*)&s0[2 * d2];
                ulonglong2 x1 = *(const ulonglong2*)&s1[2 * d2];
                ull wlo = f2pack(wq.x, wq.y), whi = f2pack(wq.z, wq.w);
                f2fma(a0, wlo, x0.x);  f2fma(a0, whi, x0.y);
                f2fma(a1, wlo, x1.x);  f2fma(a1, whi, x1.y);
            }
            part[0][g][jp] = a0;
            part[1][g][jp] = a1;
            __syncthreads();

            if (tid < 64) {
                int jl = tid >> 1, bb = tid & 1;
                float sx = 0.f, sy = 0.f;
#pragma unroll
                for (int gg = 0; gg < 8; gg++) {
                    float2 p = f2unpack(part[bb][gg][jl]);
                    sx += p.x; sy += p.y;
                }
                int j0 = 64 * (int)rank + 2 * jl;
                float h0 = tanhf(sx + bsum[l][j0]);
                float h1 = tanhf(sy + bsum[l][j0 + 1]);
                ull d0 = f2pack(h0, h0), d1 = f2pack(h1, h1);
                uint32_t a_h = smem_u32(&hs[pnew][l][bb][j0]);
#pragma unroll
                for (int rk = 0; rk < 4; rk++) {
                    st_cluster64(a_h,     (uint32_t)rk, d0);
                    st_cluster64(a_h + 8, (uint32_t)rk, d1);
                }
                if (l == 3)
                    *(float2*)(g_A + (size_t)(t * 32 + 2 * cid + bb) * 256 + j0)
                        = make_float2(h0, h1);
            }
            cluster_sync_();
        }
    }
    {
        int l2 = tid >> 6, jl = tid & 63;
        int j = 64 * (int)rank + jl;
#pragma unroll
        for (int bb = 0; bb < 2; bb++) {
            float2 v = f2unpack(hs[1][l2][bb][j]);
            out_hidden[(l2 * 32 + 2 * cid + bb) * 256 + j] = v.x;
        }
    }
}

// ---------------------------------------------------------------------------
// Decoder GEMM: out[8192,32000] = g_A[8192,256] @ dec_W[32000,256]^T + dec_b
// Legacy tensor path: mma.sync.m16n8k8 tf32 (baseline PTX; tcgen05 is not
// available through the harness's compute_103 PTX target).
// Tiles 128x128xK32; 8 warps as 2(m) x 4(n), 64x32 per warp.
// A/B staged m-major in SMEM with pitch 36 -> fragment LDS bank index is
// (4*g + t4): a perfect 32-way permutation, conflict-free.
// ---------------------------------------------------------------------------
__global__ __launch_bounds__(256, 2) void gemm_dec(
    const float* __restrict__ decW, const float* __restrict__ dec_b,
    float* __restrict__ out)
{
    __shared__ __align__(16) float As[128][36];
    __shared__ __align__(16) float Bs[128][36];

    const int tid  = threadIdx.x;
    const int warp = tid >> 5, lane = tid & 31;
    const int g    = lane >> 2, t4 = lane & 3;
    const int wm   = (warp >> 2) * 64;      // warp m offset (0 / 64)
    const int wn   = (warp & 3) * 32;       // warp n offset
    const int k4   = tid & 7;               // staging k-quad
    const int mr   = tid >> 3;              // staging row 0..31
    const int n_base = blockIdx.x * 128;
    const int m_base = blockIdx.y * 128;

    float acc[4][4][4];
#pragma unroll
    for (int i = 0; i < 4; i++)
#pragma unroll
        for (int j = 0; j < 4; j++)
#pragma unroll
            for (int e = 0; e < 4; e++) acc[i][j][e] = 0.f;

    for (int c = 0; c < 8; c++) {
        const int kc = c * 32;
        __syncthreads();
#pragma unroll
        for (int rep = 0; rep < 4; rep++) {
            int row = mr + rep * 32;
            float4 va = *(const float4*)(g_A  + (size_t)(m_base + row) * 256 + kc + k4 * 4);
            float4 vb = *(const float4*)(decW + (size_t)(n_base + row) * 256 + kc + k4 * 4);
            uint4 ta = make_uint4(cvt_tf32(va.x), cvt_tf32(va.y), cvt_tf32(va.z), cvt_tf32(va.w));
            uint4 tb = make_uint4(cvt_tf32(vb.x), cvt_tf32(vb.y), cvt_tf32(vb.z), cvt_tf32(vb.w));
            *(uint4*)&As[row][k4 * 4] = ta;
            *(uint4*)&Bs[row][k4 * 4] = tb;
        }
        __syncthreads();

#pragma unroll
        for (int ks = 0; ks < 4; ks++) {
            const int k0 = ks * 8;
            uint32_t af[4][4], bf[4][2];
#pragma unroll
            for (int mt = 0; mt < 4; mt++) {
                int row = wm + mt * 16 + g;
                af[mt][0] = __float_as_uint(As[row][k0 + t4]);
                af[mt][1] = __float_as_uint(As[row + 8][k0 + t4]);
                af[mt][2] = __float_as_uint(As[row][k0 + t4 + 4]);
                af[mt][3] = __float_as_uint(As[row + 8][k0 + t4 + 4]);
            }
#pragma unroll
            for (int nt = 0; nt < 4; nt++) {
                int col = wn + nt * 8 + g;
                bf[nt][0] = __float_as_uint(Bs[col][k0 + t4]);
                bf[nt][1] = __float_as_uint(Bs[col][k0 + t4 + 4]);
            }
#pragma unroll
            for (int mt = 0; mt < 4; mt++)
#pragma unroll
                for (int nt = 0; nt < 4; nt++)
                    mma_tf32_16x8x8(acc[mt][nt], af[mt], bf[nt]);
        }
    }

    float2 bias[4];
#pragma unroll
    for (int nt = 0; nt < 4; nt++)
        bias[nt] = *(const float2*)(dec_b + n_base + wn + nt * 8 + 2 * t4);

#pragma unroll
    for (int mt = 0; mt < 4; mt++) {
        size_t row0 = (size_t)(m_base + wm + mt * 16 + g) * NVOC;
        size_t row1 = row0 + (size_t)8 * NVOC;
#pragma unroll
        for (int nt = 0; nt < 4; nt++) {
            int col = n_base + wn + nt * 8 + 2 * t4;
            *(float2*)(out + row0 + col) =
                make_float2(acc[mt][nt][0] + bias[nt].x, acc[mt][nt][1] + bias[nt].y);
            *(float2*)(out + row1 + col) =
                make_float2(acc[mt][nt][2] + bias[nt].x, acc[mt][nt][3] + bias[nt].y);
        }
    }
}

// ---------------------------------------------------------------------------
extern "C" void kernel_launch(void* const* d_in, const int* in_sizes, int n_in,
                              void* d_out, int out_size) {
    const int*   tokens = (const int*)  d_in[0];
    const float* emb    = (const float*)d_in[1];
    const float* W_ih   = (const float*)d_in[2];
    const float* W_hh   = (const float*)d_in[3];
    const float* b_ih   = (const float*)d_in[4];
    const float* b_hh   = (const float*)d_in[5];
    const float* dec_W  = (const float*)d_in[6];
    const float* dec_b  = (const float*)d_in[7];
    (void)in_sizes; (void)n_in; (void)out_size;

    float* out        = (float*)d_out;
    float* out_hidden = out + (size_t)M_TOT * NVOC;

    pack_rnn<<<512, 256>>>(W_ih, W_hh);
    rnn_kernel<<<64, 256>>>(tokens, emb, b_ih, b_hh, out_hidden);
    gemm_dec<<<dim3(NVOC / 128, M_TOT / 128), 256>>>(dec_W, dec_b, out);
}